// round 15
// baseline (speedup 1.0000x reference)
#include <cuda_runtime.h>
#include <cuda_bf16.h>
#include <math.h>
#include <stdint.h>

#define HFD 64
#define WFD 64
#define CIN 1280
#define CCAP 256
#define NCAPS 19
#define DK 64
#define DV 16
#define NP 48              // 0..18 score-base, 19 act-logit, 20..35 V, 36..47 zero pad
#define BATCH 8
#define NINST 32
#define NPTS 256
#define NPIX (HFD*WFD)     // 4096
#define PKTOT (BATCH*NPIX*NP)
#define KC 80              // combined cols: 0..63 Wk-proj, 64..79 Wv-proj

// ---- device scratch (no cudaMalloc allowed) ----
__device__ uint32_t g_Wbh[(CIN/2)*NP];        // folded weights, bf16 hi, packed k-pairs
__device__ uint32_t g_Wbl[(CIN/2)*NP];        // bf16 lo residual, packed k-pairs
__device__ float    g_const[NP];
__device__ float    g_QWrel[2*NCAPS];         // rel-pos rows of 0.125*Q@Wk^T
__device__ float    g_Tp[4*CIN*KC];           // T partials per j-quarter (1.6 MB)
__device__ float    g_cbp[4*KC];              // column-bias partials per j-quarter
__device__ float    g_pk[2*PKTOT];            // two K-split partial buffers (12.6 MB)

__device__ __forceinline__ uint32_t packbf2(float x, float y) {
    __nv_bfloat162 h = __floats2bfloat162_rn(x, y);
    return *(uint32_t*)&h;
}

// ============ P1: T partials. grid 320 = 80 c-tiles x 4 j-quarters, 256 thr ============
// T[c][o] = sum_j Wp[j][c]*[Wk|Wv][j][o] ; this block: 16 channels, 64 j.
__global__ __launch_bounds__(256) void prep1_kernel(
    const float* __restrict__ Wp, const float* __restrict__ Wk,
    const float* __restrict__ Wv, const float* __restrict__ bp)
{
    __shared__ float wpS[64*16];   // [jj][c]
    __shared__ float kS[64*KC];    // [jj][col80]
    __shared__ float bpS[64];

    int t  = threadIdx.x;
    int ct = blockIdx.x >> 2;
    int jq = blockIdx.x & 3;
    int c0 = ct * 16;
    int j0 = jq * 64;
    int cl = t & 15;               // channel 0..15
    int cg = t >> 4;               // col group 0..15 (5 cols each)

    // Wp tile: 256 float4 (1 each)
    {
        int jj = t >> 2, c4 = (t & 3) * 4;
        *(float4*)&wpS[jj*16 + c4] = *(const float4*)&Wp[(size_t)(j0+jj)*CIN + c0 + c4];
    }
    // Wk -> kS cols 0..63: 1024 float4 (4 each)
    #pragma unroll
    for (int r = 0; r < 4; ++r) {
        int i = t + 256*r;
        int jj = i >> 4, o4 = (i & 15) * 4;
        *(float4*)&kS[jj*KC + o4] = *(const float4*)&Wk[(size_t)(j0+jj)*DK + o4];
    }
    // Wv -> kS cols 64..79: 256 float4 (1 each)
    {
        int jj = t >> 2, d4 = (t & 3) * 4;
        *(float4*)&kS[jj*KC + 64 + d4] = *(const float4*)&Wv[(size_t)(j0+jj)*DV + d4];
    }
    if (ct == 0 && t < 64) bpS[t] = bp[j0 + t];
    __syncthreads();

    float acc[5] = {0.f, 0.f, 0.f, 0.f, 0.f};
    #pragma unroll 4
    for (int jj = 0; jj < 64; ++jj) {
        float a = wpS[jj*16 + cl];
        #pragma unroll
        for (int r = 0; r < 5; ++r) acc[r] += a * kS[jj*KC + cg*5 + r];
    }
    float* dst = &g_Tp[((size_t)jq*CIN + c0 + cl)*KC + cg*5];
    #pragma unroll
    for (int r = 0; r < 5; ++r) dst[r] = acc[r];

    if (ct == 0 && t < KC) {
        float cb = 0.f;
        #pragma unroll 8
        for (int jj = 0; jj < 64; ++jj) cb += bpS[jj] * kS[jj*KC + t];
        g_cbp[jq*KC + t] = cb;
    }
}

// ============ P2: reduce partials + Q-contract + pack; block 128 = const/QWrel ============
// blocks 0..127: 5 channel-pairs x 48 cols each (threads t<240).
__global__ __launch_bounds__(256) void prep2_kernel(
    const float* __restrict__ Wa, const float* __restrict__ Q,
    const float* __restrict__ Wk, const float* __restrict__ ba,
    const float* __restrict__ bk, const float* __restrict__ bv)
{
    int t = threadIdx.x;
    int b = blockIdx.x;

    if (b < 128) {
        __shared__ float qS[NCAPS*64];
        for (int i = t; i < NCAPS*64; i += 256) qS[i] = Q[i];
        __syncthreads();
        if (t >= 240) return;
        int cpL = t / 48, col = t % 48;
        int pair = b*5 + cpL;
        int c = 2*pair;
        const float* T0 = &g_Tp[(size_t)(0*CIN + c)*KC];
        const float* T1 = &g_Tp[(size_t)(1*CIN + c)*KC];
        const float* T2 = &g_Tp[(size_t)(2*CIN + c)*KC];
        const float* T3 = &g_Tp[(size_t)(3*CIN + c)*KC];
        float s0, s1;
        if (col < NCAPS) {
            float a0 = 0.f, a1 = 0.f;
            #pragma unroll 4
            for (int o = 0; o < 64; ++o) {
                float ta = T0[o]    + T1[o]    + T2[o]    + T3[o];
                float tb = T0[KC+o] + T1[KC+o] + T2[KC+o] + T3[KC+o];
                float qq = qS[col*64 + o];
                a0 += qq * ta;
                a1 += qq * tb;
            }
            s0 = 0.125f*a0; s1 = 0.125f*a1;
        } else if (col == NCAPS) {
            s0 = Wa[c]; s1 = Wa[c + 1];
        } else if (col < 20 + DV) {
            int o = 64 + (col - 20);
            s0 = T0[o]    + T1[o]    + T2[o]    + T3[o];
            s1 = T0[KC+o] + T1[KC+o] + T2[KC+o] + T3[KC+o];
        } else { s0 = 0.f; s1 = 0.f; }
        __nv_bfloat162 h = __floats2bfloat162_rn(s0, s1);
        g_Wbh[pair*NP + col] = *(uint32_t*)&h;
        g_Wbl[pair*NP + col] =
            packbf2(s0 - __bfloat162float(h.x), s1 - __bfloat162float(h.y));
    } else {
        // const + QWrel block, warp-parallel
        __shared__ float qS[NCAPS*64];
        __shared__ float cbS[KC];
        __shared__ float bkS[64];
        __shared__ float wkrS[2*64];
        for (int i = t; i < NCAPS*64; i += 256) qS[i] = Q[i];
        if (t < KC)
            cbS[t] = g_cbp[t] + g_cbp[KC + t] + g_cbp[2*KC + t] + g_cbp[3*KC + t];
        if (t >= 80 && t < 144) bkS[t - 80] = bk[t - 80];
        if (t >= 128 && t < 256) wkrS[t - 128] = Wk[(size_t)256*DK + (t - 128)];
        __syncthreads();

        int w = t >> 5, lane = t & 31;
        for (int o = w; o < NP; o += 8) {
            float s = 0.f;
            if (o < NCAPS) {
                float a = 0.f;
                for (int k = lane; k < 64; k += 32) a += qS[o*64 + k] * (cbS[k] + bkS[k]);
                #pragma unroll
                for (int off = 16; off; off >>= 1) a += __shfl_xor_sync(0xffffffffu, a, off);
                s = 0.125f * a;
            } else if (o == NCAPS) s = ba[0];
            else if (o < 20 + DV) s = cbS[64 + (o - 20)] + bv[o - 20];
            if (lane == 0) g_const[o] = s;
        }
        for (int i = w; i < 2*NCAPS; i += 8) {
            int cc = i % NCAPS, which = i / NCAPS;
            float a = 0.f;
            for (int k = lane; k < 64; k += 32) a += qS[cc*64 + k] * wkrS[which*64 + k];
            #pragma unroll
            for (int off = 16; off; off >>= 1) a += __shfl_xor_sync(0xffffffffu, a, off);
            if (lane == 0) g_QWrel[which*NCAPS + cc] = 0.125f * a;
        }
    }
}

// ============ GEMM: pk = feat @ Wfold, 3xBF16 mma, BM=64, K-split 2, grid 1024 (verified) ============
#define BM 64
#define BK 16
#define AS_STRIDE 68
#define BS_STRIDE 56
#define NKCH_H 40          // k-chunks per split (K=640 each)

#define CP_ASYNC16(dst_s32, src) \
    asm volatile("cp.async.cg.shared.global [%0], [%1], 16;\n" :: "r"(dst_s32), "l"(src))
#define CP_COMMIT() asm volatile("cp.async.commit_group;\n")

__device__ __forceinline__ void mma_bf16(float* d, const uint32_t* a, uint32_t b0, uint32_t b1) {
    asm volatile(
        "mma.sync.aligned.m16n8k16.row.col.f32.bf16.bf16.f32 "
        "{%0,%1,%2,%3},{%4,%5,%6,%7},{%8,%9},{%0,%1,%2,%3};\n"
        : "+f"(d[0]), "+f"(d[1]), "+f"(d[2]), "+f"(d[3])
        : "r"(a[0]), "r"(a[1]), "r"(a[2]), "r"(a[3]), "r"(b0), "r"(b1));
}

__global__ __launch_bounds__(128) void gemm_kernel(const float* __restrict__ feat) {
    __shared__ __align__(16) float smem[4016];
    int t = threadIdx.x;
    int mtile = blockIdx.x >> 1;
    int split = blockIdx.x & 1;
    int m0 = mtile * BM;
    int b  = m0 / NPIX;
    int pix0 = m0 % NPIX;
    int kbase = split * (CIN/2);         // 0 or 640
    const float* aBase = feat + (size_t)b*CIN*NPIX + pix0;

    if (t < NP) smem[3968 + t] = split ? 0.f : g_const[t];

    int lane = t & 31, w = t >> 5;
    int gid = lane >> 2, tig = lane & 3;
    int wm = w * 16;

    uint32_t s_as = (uint32_t)__cvta_generic_to_shared(smem);
    uint32_t s_bh = s_as + 2176*4;
    uint32_t s_bl = s_as + 3072*4;

    int a_kk0 = t >> 4;              // 0..7 (second: +8)
    int a_m0  = (t & 15) * 4;
    int b_kp  = t / 12;              // 0..7 (t<96)
    int b_n0  = (t % 12) * 4;

#define LOAD_STAGE(p, k0)                                                            \
    do {                                                                             \
        CP_ASYNC16(s_as + ((p)*1088 + a_kk0*AS_STRIDE + a_m0)*4,                     \
                   aBase + (size_t)((k0)+a_kk0)*NPIX + a_m0);                        \
        CP_ASYNC16(s_as + ((p)*1088 + (a_kk0+8)*AS_STRIDE + a_m0)*4,                 \
                   aBase + (size_t)((k0)+a_kk0+8)*NPIX + a_m0);                      \
        if (t < 96) {                                                                \
            CP_ASYNC16(s_bh + ((p)*448 + b_kp*BS_STRIDE + b_n0)*4,                   \
                       &g_Wbh[((k0)/2 + b_kp)*NP + b_n0]);                           \
            CP_ASYNC16(s_bl + ((p)*448 + b_kp*BS_STRIDE + b_n0)*4,                   \
                       &g_Wbl[((k0)/2 + b_kp)*NP + b_n0]);                           \
        }                                                                            \
        CP_COMMIT();                                                                 \
    } while (0)

    LOAD_STAGE(0, kbase);

    float d[6][4];
    #pragma unroll
    for (int nt = 0; nt < 6; ++nt)
        #pragma unroll
        for (int i = 0; i < 4; ++i) d[nt][i] = 0.f;

    for (int kc = 0; kc < NKCH_H; ++kc) {
        if (kc + 1 < NKCH_H) {
            LOAD_STAGE((kc+1) & 1, kbase + (kc+1)*BK);
            asm volatile("cp.async.wait_group 1;\n");
        } else {
            asm volatile("cp.async.wait_group 0;\n");
        }
        __syncthreads();

        const float*    As_ = smem + (kc&1)*1088;
        const uint32_t* Bh  = (const uint32_t*)(smem + 2176) + (kc&1)*448;
        const uint32_t* Bl  = (const uint32_t*)(smem + 3072) + (kc&1)*448;

        int m = wm + gid;
        float L00 = As_[(2*tig  )*AS_STRIDE + m];
        float L01 = As_[(2*tig+1)*AS_STRIDE + m];
        float L08 = As_[(2*tig+8)*AS_STRIDE + m];
        float L09 = As_[(2*tig+9)*AS_STRIDE + m];
        float M00 = As_[(2*tig  )*AS_STRIDE + m + 8];
        float M01 = As_[(2*tig+1)*AS_STRIDE + m + 8];
        float M08 = As_[(2*tig+8)*AS_STRIDE + m + 8];
        float M09 = As_[(2*tig+9)*AS_STRIDE + m + 8];

        uint32_t ah[4], al[4];
        {
            __nv_bfloat162 h;
            h = __floats2bfloat162_rn(L00, L01); ah[0] = *(uint32_t*)&h;
            al[0] = packbf2(L00 - __bfloat162float(h.x), L01 - __bfloat162float(h.y));
            h = __floats2bfloat162_rn(M00, M01); ah[1] = *(uint32_t*)&h;
            al[1] = packbf2(M00 - __bfloat162float(h.x), M01 - __bfloat162float(h.y));
            h = __floats2bfloat162_rn(L08, L09); ah[2] = *(uint32_t*)&h;
            al[2] = packbf2(L08 - __bfloat162float(h.x), L09 - __bfloat162float(h.y));
            h = __floats2bfloat162_rn(M08, M09); ah[3] = *(uint32_t*)&h;
            al[3] = packbf2(M08 - __bfloat162float(h.x), M09 - __bfloat162float(h.y));
        }

        #pragma unroll
        for (int nt = 0; nt < 6; ++nt) {
            int n = nt*8 + gid;
            uint32_t bh0 = Bh[ tig   *BS_STRIDE + n];
            uint32_t bh1 = Bh[(tig+4)*BS_STRIDE + n];
            uint32_t bl0 = Bl[ tig   *BS_STRIDE + n];
            uint32_t bl1 = Bl[(tig+4)*BS_STRIDE + n];
            mma_bf16(d[nt], ah, bh0, bh1);
            mma_bf16(d[nt], ah, bl0, bl1);
            mma_bf16(d[nt], al, bh0, bh1);
        }
        __syncthreads();
    }

    float* Cs = smem;
    #pragma unroll
    for (int nt = 0; nt < 6; ++nt) {
        int col = nt*8 + tig*2;
        Cs[(wm + gid    )*NP + col    ] = d[nt][0];
        Cs[(wm + gid    )*NP + col + 1] = d[nt][1];
        Cs[(wm + gid + 8)*NP + col    ] = d[nt][2];
        Cs[(wm + gid + 8)*NP + col + 1] = d[nt][3];
    }
    __syncthreads();
    const float4* csts4 = (const float4*)(smem + 3968);
    float4* outBase = (float4*)(g_pk + (size_t)split*PKTOT + (size_t)m0*NP);
    #pragma unroll
    for (int it = 0; it < 6; ++it) {
        int i = t + 128*it;              // 768 float4 total
        float4 v = ((const float4*)Cs)[i];
        float4 c = csts4[i % 12];
        v.x += c.x; v.y += c.y; v.z += c.z; v.w += c.w;
        outBase[i] = v;
    }
}

// ============ route: dedupe + softmax routing (sums two K-split partials, verified) ============
__global__ __launch_bounds__(256) void route_kernel(
    const int* __restrict__ pts,
    const float* __restrict__ Wv,
    const float* __restrict__ Wl,
    const float* __restrict__ bl,
    float* __restrict__ out)
{
    __shared__ unsigned bitmap[NPIX/32];
    __shared__ int counts[NPIX/32];
    __shared__ int offs[NPIX/32 + 1];
    __shared__ unsigned short cells[NPTS];
    __shared__ int sumY, sumX;
    __shared__ float scores[NCAPS][NPTS];
    __shared__ float vmatS[DV][NPTS];
    __shared__ float qwy[NCAPS], qwx[NCAPS];
    __shared__ float relVy[DV], relVx[DV], Wls[DV];

    int t  = threadIdx.x;
    int bi = blockIdx.x;
    const int* pbase = pts + (size_t)bi*2*NPTS;

    if (t < NPIX/32) bitmap[t] = 0u;
    if (t < NCAPS) { qwy[t] = g_QWrel[t]; qwx[t] = g_QWrel[NCAPS + t]; }
    if (t < DV) { relVy[t] = Wv[256*DV + t]; relVx[t] = Wv[257*DV + t]; Wls[t] = Wl[t]; }
    if (t == 0) { sumY = 0; sumX = 0; }
    __syncthreads();

    {
        int y = pbase[t] >> 4;
        int x = pbase[NPTS + t] >> 4;
        int key = y*WFD + x;
        atomicOr(&bitmap[key >> 5], 1u << (key & 31));
    }
    __syncthreads();
    if (t < NPIX/32) counts[t] = __popc(bitmap[t]);
    __syncthreads();
    if (t < 32) {
        int c0 = counts[t*4], c1 = counts[t*4+1], c2 = counts[t*4+2], c3 = counts[t*4+3];
        int s = c0 + c1 + c2 + c3;
        int run = s;
        #pragma unroll
        for (int off = 1; off < 32; off <<= 1) {
            int v = __shfl_up_sync(0xffffffffu, run, off);
            if (t >= off) run += v;
        }
        int excl = run - s;
        offs[t*4]   = excl;
        offs[t*4+1] = excl + c0;
        offs[t*4+2] = excl + c0 + c1;
        offs[t*4+3] = excl + c0 + c1 + c2;
        if (t == 31) offs[128] = run;
    }
    __syncthreads();
    if (t < NPIX/32) {
        unsigned bits = bitmap[t];
        int idx = offs[t];
        int sy = 0, sx = 0;
        while (bits) {
            int bpos = __ffs(bits) - 1;
            bits &= bits - 1;
            int cell = t*32 + bpos;
            cells[idx++] = (unsigned short)cell;
            sy += cell >> 6;
            sx += cell & 63;
        }
        if (counts[t]) { atomicAdd(&sumY, sy); atomicAdd(&sumX, sx); }
    }
    __syncthreads();

    int U = offs[NPIX/32];
    float nfl = (float)(U > 0 ? U : 1);
    float meanY = (float)sumY / nfl;
    float meanX = (float)sumX / nfl;

    if (t < U) {
        int cell = cells[t];
        size_t base = ((size_t)(bi >> 5)*NPIX + cell)*NP;
        const float4* pk4a = (const float4*)&g_pk[base];
        const float4* pk4b = (const float4*)&g_pk[PKTOT + base];
        float4 q[9];
        #pragma unroll
        for (int i = 0; i < 9; ++i) {
            float4 a = pk4a[i], b4 = pk4b[i];
            a.x += b4.x; a.y += b4.y; a.z += b4.z; a.w += b4.w;
            q[i] = a;
        }
        const float* pk = (const float*)q;

        float ry = ((float)(cell >> 6) - meanY) * (1.f/HFD);
        float rx = ((float)(cell & 63) - meanX) * (1.f/WFD);
        float act = 1.f/(1.f + expf(-pk[19]));
        float la  = logf(act + 1e-6f);
        #pragma unroll
        for (int c = 0; c < NCAPS; ++c)
            scores[c][t] = pk[c] + ry*qwy[c] + rx*qwx[c] + la;
        #pragma unroll
        for (int dd = 0; dd < DV; ++dd)
            vmatS[dd][t] = pk[20 + dd] + ry*relVy[dd] + rx*relVx[dd];
    }
    __syncthreads();

    int warp = t >> 5, lane = t & 31;
    for (int c = warp; c < NCAPS; c += 8) {
        float mx = -1e30f;
        for (int j = lane; j < U; j += 32) mx = fmaxf(mx, scores[c][j]);
        #pragma unroll
        for (int off = 16; off; off >>= 1) mx = fmaxf(mx, __shfl_xor_sync(0xffffffffu, mx, off));
        float se = 0.f;
        float acc[DV];
        #pragma unroll
        for (int dd = 0; dd < DV; ++dd) acc[dd] = 0.f;
        for (int j = lane; j < U; j += 32) {
            float e = expf(scores[c][j] - mx);
            se += e;
            #pragma unroll
            for (int dd = 0; dd < DV; ++dd) acc[dd] += e*vmatS[dd][j];
        }
        #pragma unroll
        for (int off = 16; off; off >>= 1) {
            se += __shfl_xor_sync(0xffffffffu, se, off);
            #pragma unroll
            for (int dd = 0; dd < DV; ++dd) acc[dd] += __shfl_xor_sync(0xffffffffu, acc[dd], off);
        }
        if (lane == 0) {
            float o = bl[0];
            float inv = 1.f/se;
            #pragma unroll
            for (int dd = 0; dd < DV; ++dd) o += (acc[dd]*inv)*Wls[dd];
            out[bi*NCAPS + c] = 1.f/(1.f + expf(-o));
        }
    }
}

extern "C" void kernel_launch(void* const* d_in, const int* in_sizes, int n_in,
                              void* d_out, int out_size) {
    const float* feat = (const float*)d_in[0];
    const float* Wp   = (const float*)d_in[1];
    const float* bp   = (const float*)d_in[2];
    const float* Wa   = (const float*)d_in[3];
    const float* ba   = (const float*)d_in[4];
    const float* Q    = (const float*)d_in[5];
    const float* Wk   = (const float*)d_in[6];
    const float* bk   = (const float*)d_in[7];
    const float* Wv   = (const float*)d_in[8];
    const float* bv   = (const float*)d_in[9];
    const float* Wl   = (const float*)d_in[10];
    const float* bl   = (const float*)d_in[11];
    const int*   pts  = (const int*)d_in[12];
    float* out = (float*)d_out;

    prep1_kernel<<<320, 256>>>(Wp, Wk, Wv, bp);
    prep2_kernel<<<129, 256>>>(Wa, Q, Wk, ba, bk, bv);
    gemm_kernel<<<(BATCH*NPIX)/BM * 2, 128>>>(feat);
    route_kernel<<<BATCH*NINST, 256>>>(pts, Wv, Wl, bl, out);
}

// round 16
// speedup vs baseline: 1.4720x; 1.4720x over previous
#include <cuda_runtime.h>
#include <cuda_bf16.h>
#include <math.h>
#include <stdint.h>

#define HFD 64
#define WFD 64
#define CIN 1280
#define CCAP 256
#define NCAPS 19
#define DK 64
#define DV 16
#define NP 48              // 0..18 score-base, 19 act-logit, 20..35 V, 36..47 zero pad
#define BATCH 8
#define NINST 32
#define NPTS 256
#define NPIX (HFD*WFD)     // 4096
#define PKTOT (BATCH*NPIX*NP)

// ---- device scratch (no cudaMalloc allowed) ----
__device__ uint32_t g_Wbh[(CIN/2)*NP];        // folded weights, bf16 hi, packed k-pairs
__device__ uint32_t g_Wbl[(CIN/2)*NP];        // bf16 lo residual, packed k-pairs
__device__ float    g_const[NP];
__device__ float    g_QWrel[2*NCAPS];         // rel-pos rows of 0.125*Q@Wk^T
__device__ float    g_pk[2*PKTOT];            // two K-split partial buffers (12.6 MB)

__device__ __forceinline__ uint32_t packbf2(float x, float y) {
    __nv_bfloat162 h = __floats2bfloat162_rn(x, y);
    return *(uint32_t*)&h;
}

// ============ prep v4: qw + fold + const, grid 160, 512 thr, 2 j-tiles of 128, padded qS ============
// T[c][o] = sum_j Wp[j][c]*Wk[j][o] (o<64) ; V[c][d] = sum_j Wp[j][c]*Wv[j][d]
// Wf[c][col<19] = 0.125*sum_o Q[col][o]*T[c][o] ; col 19 = Wa[c] ; cols 20..35 = V
#define CT 8                // channels per block
#define KC 80               // combined cols: 0..63 Wk, 64..79 Wv
__global__ __launch_bounds__(512) void prep_kernel(
    const float* __restrict__ Wp, const float* __restrict__ Wa,
    const float* __restrict__ Q,  const float* __restrict__ Wk,
    const float* __restrict__ Wv, const float* __restrict__ bp,
    const float* __restrict__ ba, const float* __restrict__ bk,
    const float* __restrict__ bv)
{
    __shared__ float wpS[128*CT];     // [jj][c]                1024
    __shared__ float kS[128*KC];      // [jj][col80]            10240
    __shared__ float bpS[128];
    __shared__ float qS[NCAPS*65];    // padded stride 65       1235
    __shared__ float TSp[4*CT*81];    // [js][c][col80] pad 81  2592
    __shared__ float TS[CT*81];       // reduced                648
    __shared__ float cbS[KC];

    int t  = threadIdx.x;
    int c0 = blockIdx.x * CT;
    int cl = t & 7;                   // channel 0..7
    int cg = (t >> 3) & 15;           // col group 0..15
    int g5 = cg * 5;                  // col base 0..75
    int js = t >> 7;                  // j-quarter 0..3 (32 j each per tile)
    bool blk0 = (blockIdx.x == 0);

    for (int i = t; i < NCAPS*64; i += 512) {
        int row = i >> 6, o = i & 63;
        qS[row*65 + o] = Q[i];
    }

    float acc[5] = {0.f, 0.f, 0.f, 0.f, 0.f};
    float cb = 0.f;

    for (int tile = 0; tile < 2; ++tile) {
        int j0 = tile * 128;
        __syncthreads();
        // Wp tile 128x8 = 256 float4 (t<256)
        if (t < 256) {
            int jj = t >> 1, c4 = (t & 1) * 4;
            *(float4*)&wpS[jj*CT + c4] = *(const float4*)&Wp[(size_t)(j0+jj)*CIN + c0 + c4];
        }
        // Wk into kS cols 0..63: 2048 float4 (4 each)
        #pragma unroll
        for (int r = 0; r < 4; ++r) {
            int i = t + 512*r;
            int jj = i >> 4, o4 = (i & 15) * 4;
            *(float4*)&kS[jj*KC + o4] = *(const float4*)&Wk[(size_t)(j0+jj)*DK + o4];
        }
        // Wv into kS cols 64..79: 512 float4 (1 each)
        {
            int jj = t >> 2, d4 = (t & 3) * 4;
            *(float4*)&kS[jj*KC + 64 + d4] = *(const float4*)&Wv[(size_t)(j0+jj)*DV + d4];
        }
        if (blk0 && t >= 384) bpS[t - 384] = bp[j0 + (t - 384)];
        __syncthreads();

        // main accumulation: this thread's 32-j slice
        int jb = js * 32;
        #pragma unroll 4
        for (int u = 0; u < 32; ++u) {
            int jj = jb + u;
            float a = wpS[jj*CT + cl];
            #pragma unroll
            for (int r = 0; r < 5; ++r) acc[r] += a * kS[jj*KC + g5 + r];
        }
        // block 0: column-bias fold (80 threads, full 128 j per tile)
        if (blk0 && t < KC) {
            #pragma unroll 8
            for (int jj = 0; jj < 128; ++jj) cb += bpS[jj] * kS[jj*KC + t];
        }
    }
    __syncthreads();
    #pragma unroll
    for (int r = 0; r < 5; ++r) TSp[(js*CT + cl)*81 + g5 + r] = acc[r];
    if (blk0 && t < KC) cbS[t] = cb;
    __syncthreads();

    // reduce 4 j-partials: 8*80 outputs
    for (int i = t; i < CT*KC; i += 512) {
        int c = i / KC, o = i % KC;
        TS[c*81 + o] = TSp[(0*CT + c)*81 + o] + TSp[(1*CT + c)*81 + o]
                     + TSp[(2*CT + c)*81 + o] + TSp[(3*CT + c)*81 + o];
    }
    __syncthreads();

    // output: 4 channel-pairs x 48 cols = 192 outputs
    if (t < (CT/2)*NP) {
        int cp = t / NP, col = t % NP;
        int c = c0 + 2*cp;
        float s0, s1;
        if (col < NCAPS) {
            float a0 = 0.f, a1 = 0.f;
            const float* q  = &qS[col*65];
            const float* t0 = &TS[(2*cp  )*81];
            const float* t1 = &TS[(2*cp+1)*81];
            #pragma unroll 8
            for (int o = 0; o < 64; ++o) {
                float qq = q[o];
                a0 += qq * t0[o];
                a1 += qq * t1[o];
            }
            s0 = 0.125f*a0; s1 = 0.125f*a1;
        } else if (col == NCAPS) {
            s0 = Wa[c]; s1 = Wa[c + 1];
        } else if (col < 20 + DV) {
            int d = col - 20;
            s0 = TS[(2*cp)*81 + 64 + d]; s1 = TS[(2*cp+1)*81 + 64 + d];
        } else { s0 = 0.f; s1 = 0.f; }
        __nv_bfloat162 h = __floats2bfloat162_rn(s0, s1);
        g_Wbh[(c >> 1)*NP + col] = *(uint32_t*)&h;
        g_Wbl[(c >> 1)*NP + col] =
            packbf2(s0 - __bfloat162float(h.x), s1 - __bfloat162float(h.y));
    }

    if (blk0) {
        if (t >= 256 && t < 256 + NP) {
            int o = t - 256;
            float s;
            if (o < NCAPS) {
                float a = 0.f;
                #pragma unroll 8
                for (int k = 0; k < 64; ++k) a += qS[o*65 + k] * (cbS[k] + bk[k]);
                s = 0.125f * a;
            } else if (o == NCAPS) s = ba[0];
            else if (o < 20 + DV) s = cbS[64 + (o - 20)] + bv[o - 20];
            else s = 0.f;
            g_const[o] = s;
        }
        if (t >= 320 && t < 320 + 2*NCAPS) {
            int i = t - 320;
            int cc = i % NCAPS, which = i / NCAPS;
            const float* wkrow = Wk + (size_t)(256 + which)*DK;
            float s = 0.f;
            #pragma unroll 8
            for (int o = 0; o < 64; ++o) s += qS[cc*65 + o] * wkrow[o];
            g_QWrel[which*NCAPS + cc] = 0.125f * s;
        }
    }
}

// ============ GEMM: pk = feat @ Wfold, 3xBF16 mma, BM=64, K-split 2, grid 1024 (verified) ============
#define BM 64
#define BK 16
#define AS_STRIDE 68
#define BS_STRIDE 56
#define NKCH_H 40          // k-chunks per split (K=640 each)

#define CP_ASYNC16(dst_s32, src) \
    asm volatile("cp.async.cg.shared.global [%0], [%1], 16;\n" :: "r"(dst_s32), "l"(src))
#define CP_COMMIT() asm volatile("cp.async.commit_group;\n")

__device__ __forceinline__ void mma_bf16(float* d, const uint32_t* a, uint32_t b0, uint32_t b1) {
    asm volatile(
        "mma.sync.aligned.m16n8k16.row.col.f32.bf16.bf16.f32 "
        "{%0,%1,%2,%3},{%4,%5,%6,%7},{%8,%9},{%0,%1,%2,%3};\n"
        : "+f"(d[0]), "+f"(d[1]), "+f"(d[2]), "+f"(d[3])
        : "r"(a[0]), "r"(a[1]), "r"(a[2]), "r"(a[3]), "r"(b0), "r"(b1));
}

__global__ __launch_bounds__(128) void gemm_kernel(const float* __restrict__ feat) {
    __shared__ __align__(16) float smem[4016];
    int t = threadIdx.x;
    int mtile = blockIdx.x >> 1;
    int split = blockIdx.x & 1;
    int m0 = mtile * BM;
    int b  = m0 / NPIX;
    int pix0 = m0 % NPIX;
    int kbase = split * (CIN/2);         // 0 or 640
    const float* aBase = feat + (size_t)b*CIN*NPIX + pix0;

    if (t < NP) smem[3968 + t] = split ? 0.f : g_const[t];

    int lane = t & 31, w = t >> 5;
    int gid = lane >> 2, tig = lane & 3;
    int wm = w * 16;

    uint32_t s_as = (uint32_t)__cvta_generic_to_shared(smem);
    uint32_t s_bh = s_as + 2176*4;
    uint32_t s_bl = s_as + 3072*4;

    int a_kk0 = t >> 4;              // 0..7 (second: +8)
    int a_m0  = (t & 15) * 4;
    int b_kp  = t / 12;              // 0..7 (t<96)
    int b_n0  = (t % 12) * 4;

#define LOAD_STAGE(p, k0)                                                            \
    do {                                                                             \
        CP_ASYNC16(s_as + ((p)*1088 + a_kk0*AS_STRIDE + a_m0)*4,                     \
                   aBase + (size_t)((k0)+a_kk0)*NPIX + a_m0);                        \
        CP_ASYNC16(s_as + ((p)*1088 + (a_kk0+8)*AS_STRIDE + a_m0)*4,                 \
                   aBase + (size_t)((k0)+a_kk0+8)*NPIX + a_m0);                      \
        if (t < 96) {                                                                \
            CP_ASYNC16(s_bh + ((p)*448 + b_kp*BS_STRIDE + b_n0)*4,                   \
                       &g_Wbh[((k0)/2 + b_kp)*NP + b_n0]);                           \
            CP_ASYNC16(s_bl + ((p)*448 + b_kp*BS_STRIDE + b_n0)*4,                   \
                       &g_Wbl[((k0)/2 + b_kp)*NP + b_n0]);                           \
        }                                                                            \
        CP_COMMIT();                                                                 \
    } while (0)

    LOAD_STAGE(0, kbase);

    float d[6][4];
    #pragma unroll
    for (int nt = 0; nt < 6; ++nt)
        #pragma unroll
        for (int i = 0; i < 4; ++i) d[nt][i] = 0.f;

    for (int kc = 0; kc < NKCH_H; ++kc) {
        if (kc + 1 < NKCH_H) {
            LOAD_STAGE((kc+1) & 1, kbase + (kc+1)*BK);
            asm volatile("cp.async.wait_group 1;\n");
        } else {
            asm volatile("cp.async.wait_group 0;\n");
        }
        __syncthreads();

        const float*    As_ = smem + (kc&1)*1088;
        const uint32_t* Bh  = (const uint32_t*)(smem + 2176) + (kc&1)*448;
        const uint32_t* Bl  = (const uint32_t*)(smem + 3072) + (kc&1)*448;

        int m = wm + gid;
        float L00 = As_[(2*tig  )*AS_STRIDE + m];
        float L01 = As_[(2*tig+1)*AS_STRIDE + m];
        float L08 = As_[(2*tig+8)*AS_STRIDE + m];
        float L09 = As_[(2*tig+9)*AS_STRIDE + m];
        float M00 = As_[(2*tig  )*AS_STRIDE + m + 8];
        float M01 = As_[(2*tig+1)*AS_STRIDE + m + 8];
        float M08 = As_[(2*tig+8)*AS_STRIDE + m + 8];
        float M09 = As_[(2*tig+9)*AS_STRIDE + m + 8];

        uint32_t ah[4], al[4];
        {
            __nv_bfloat162 h;
            h = __floats2bfloat162_rn(L00, L01); ah[0] = *(uint32_t*)&h;
            al[0] = packbf2(L00 - __bfloat162float(h.x), L01 - __bfloat162float(h.y));
            h = __floats2bfloat162_rn(M00, M01); ah[1] = *(uint32_t*)&h;
            al[1] = packbf2(M00 - __bfloat162float(h.x), M01 - __bfloat162float(h.y));
            h = __floats2bfloat162_rn(L08, L09); ah[2] = *(uint32_t*)&h;
            al[2] = packbf2(L08 - __bfloat162float(h.x), L09 - __bfloat162float(h.y));
            h = __floats2bfloat162_rn(M08, M09); ah[3] = *(uint32_t*)&h;
            al[3] = packbf2(M08 - __bfloat162float(h.x), M09 - __bfloat162float(h.y));
        }

        #pragma unroll
        for (int nt = 0; nt < 6; ++nt) {
            int n = nt*8 + gid;
            uint32_t bh0 = Bh[ tig   *BS_STRIDE + n];
            uint32_t bh1 = Bh[(tig+4)*BS_STRIDE + n];
            uint32_t bl0 = Bl[ tig   *BS_STRIDE + n];
            uint32_t bl1 = Bl[(tig+4)*BS_STRIDE + n];
            mma_bf16(d[nt], ah, bh0, bh1);
            mma_bf16(d[nt], ah, bl0, bl1);
            mma_bf16(d[nt], al, bh0, bh1);
        }
        __syncthreads();
    }

    float* Cs = smem;
    #pragma unroll
    for (int nt = 0; nt < 6; ++nt) {
        int col = nt*8 + tig*2;
        Cs[(wm + gid    )*NP + col    ] = d[nt][0];
        Cs[(wm + gid    )*NP + col + 1] = d[nt][1];
        Cs[(wm + gid + 8)*NP + col    ] = d[nt][2];
        Cs[(wm + gid + 8)*NP + col + 1] = d[nt][3];
    }
    __syncthreads();
    const float4* csts4 = (const float4*)(smem + 3968);
    float4* outBase = (float4*)(g_pk + (size_t)split*PKTOT + (size_t)m0*NP);
    #pragma unroll
    for (int it = 0; it < 6; ++it) {
        int i = t + 128*it;              // 768 float4 total
        float4 v = ((const float4*)Cs)[i];
        float4 c = csts4[i % 12];
        v.x += c.x; v.y += c.y; v.z += c.z; v.w += c.w;
        outBase[i] = v;
    }
}

// ============ route: dedupe + softmax routing (sums two K-split partials, verified) ============
__global__ __launch_bounds__(256) void route_kernel(
    const int* __restrict__ pts,
    const float* __restrict__ Wv,
    const float* __restrict__ Wl,
    const float* __restrict__ bl,
    float* __restrict__ out)
{
    __shared__ unsigned bitmap[NPIX/32];
    __shared__ int counts[NPIX/32];
    __shared__ int offs[NPIX/32 + 1];
    __shared__ unsigned short cells[NPTS];
    __shared__ int sumY, sumX;
    __shared__ float scores[NCAPS][NPTS];
    __shared__ float vmatS[DV][NPTS];
    __shared__ float qwy[NCAPS], qwx[NCAPS];
    __shared__ float relVy[DV], relVx[DV], Wls[DV];

    int t  = threadIdx.x;
    int bi = blockIdx.x;
    const int* pbase = pts + (size_t)bi*2*NPTS;

    if (t < NPIX/32) bitmap[t] = 0u;
    if (t < NCAPS) { qwy[t] = g_QWrel[t]; qwx[t] = g_QWrel[NCAPS + t]; }
    if (t < DV) { relVy[t] = Wv[256*DV + t]; relVx[t] = Wv[257*DV + t]; Wls[t] = Wl[t]; }
    if (t == 0) { sumY = 0; sumX = 0; }
    __syncthreads();

    {
        int y = pbase[t] >> 4;
        int x = pbase[NPTS + t] >> 4;
        int key = y*WFD + x;
        atomicOr(&bitmap[key >> 5], 1u << (key & 31));
    }
    __syncthreads();
    if (t < NPIX/32) counts[t] = __popc(bitmap[t]);
    __syncthreads();
    if (t < 32) {
        int c0 = counts[t*4], c1 = counts[t*4+1], c2 = counts[t*4+2], c3 = counts[t*4+3];
        int s = c0 + c1 + c2 + c3;
        int run = s;
        #pragma unroll
        for (int off = 1; off < 32; off <<= 1) {
            int v = __shfl_up_sync(0xffffffffu, run, off);
            if (t >= off) run += v;
        }
        int excl = run - s;
        offs[t*4]   = excl;
        offs[t*4+1] = excl + c0;
        offs[t*4+2] = excl + c0 + c1;
        offs[t*4+3] = excl + c0 + c1 + c2;
        if (t == 31) offs[128] = run;
    }
    __syncthreads();
    if (t < NPIX/32) {
        unsigned bits = bitmap[t];
        int idx = offs[t];
        int sy = 0, sx = 0;
        while (bits) {
            int bpos = __ffs(bits) - 1;
            bits &= bits - 1;
            int cell = t*32 + bpos;
            cells[idx++] = (unsigned short)cell;
            sy += cell >> 6;
            sx += cell & 63;
        }
        if (counts[t]) { atomicAdd(&sumY, sy); atomicAdd(&sumX, sx); }
    }
    __syncthreads();

    int U = offs[NPIX/32];
    float nfl = (float)(U > 0 ? U : 1);
    float meanY = (float)sumY / nfl;
    float meanX = (float)sumX / nfl;

    if (t < U) {
        int cell = cells[t];
        size_t base = ((size_t)(bi >> 5)*NPIX + cell)*NP;
        const float4* pk4a = (const float4*)&g_pk[base];
        const float4* pk4b = (const float4*)&g_pk[PKTOT + base];
        float4 q[9];
        #pragma unroll
        for (int i = 0; i < 9; ++i) {
            float4 a = pk4a[i], b4 = pk4b[i];
            a.x += b4.x; a.y += b4.y; a.z += b4.z; a.w += b4.w;
            q[i] = a;
        }
        const float* pk = (const float*)q;

        float ry = ((float)(cell >> 6) - meanY) * (1.f/HFD);
        float rx = ((float)(cell & 63) - meanX) * (1.f/WFD);
        float act = 1.f/(1.f + expf(-pk[19]));
        float la  = logf(act + 1e-6f);
        #pragma unroll
        for (int c = 0; c < NCAPS; ++c)
            scores[c][t] = pk[c] + ry*qwy[c] + rx*qwx[c] + la;
        #pragma unroll
        for (int dd = 0; dd < DV; ++dd)
            vmatS[dd][t] = pk[20 + dd] + ry*relVy[dd] + rx*relVx[dd];
    }
    __syncthreads();

    int warp = t >> 5, lane = t & 31;
    for (int c = warp; c < NCAPS; c += 8) {
        float mx = -1e30f;
        for (int j = lane; j < U; j += 32) mx = fmaxf(mx, scores[c][j]);
        #pragma unroll
        for (int off = 16; off; off >>= 1) mx = fmaxf(mx, __shfl_xor_sync(0xffffffffu, mx, off));
        float se = 0.f;
        float acc[DV];
        #pragma unroll
        for (int dd = 0; dd < DV; ++dd) acc[dd] = 0.f;
        for (int j = lane; j < U; j += 32) {
            float e = expf(scores[c][j] - mx);
            se += e;
            #pragma unroll
            for (int dd = 0; dd < DV; ++dd) acc[dd] += e*vmatS[dd][j];
        }
        #pragma unroll
        for (int off = 16; off; off >>= 1) {
            se += __shfl_xor_sync(0xffffffffu, se, off);
            #pragma unroll
            for (int dd = 0; dd < DV; ++dd) acc[dd] += __shfl_xor_sync(0xffffffffu, acc[dd], off);
        }
        if (lane == 0) {
            float o = bl[0];
            float inv = 1.f/se;
            #pragma unroll
            for (int dd = 0; dd < DV; ++dd) o += (acc[dd]*inv)*Wls[dd];
            out[bi*NCAPS + c] = 1.f/(1.f + expf(-o));
        }
    }
}

extern "C" void kernel_launch(void* const* d_in, const int* in_sizes, int n_in,
                              void* d_out, int out_size) {
    const float* feat = (const float*)d_in[0];
    const float* Wp   = (const float*)d_in[1];
    const float* bp   = (const float*)d_in[2];
    const float* Wa   = (const float*)d_in[3];
    const float* ba   = (const float*)d_in[4];
    const float* Q    = (const float*)d_in[5];
    const float* Wk   = (const float*)d_in[6];
    const float* bk   = (const float*)d_in[7];
    const float* Wv   = (const float*)d_in[8];
    const float* bv   = (const float*)d_in[9];
    const float* Wl   = (const float*)d_in[10];
    const float* bl   = (const float*)d_in[11];
    const int*   pts  = (const int*)d_in[12];
    float* out = (float*)d_out;

    prep_kernel<<<CIN/CT, 512>>>(Wp, Wa, Q, Wk, Wv, bp, ba, bk, bv);
    gemm_kernel<<<(BATCH*NPIX)/BM * 2, 128>>>(feat);
    route_kernel<<<BATCH*NINST, 256>>>(pts, Wv, Wl, bl, out);
}

// round 17
// speedup vs baseline: 1.4801x; 1.0055x over previous
#include <cuda_runtime.h>
#include <cuda_bf16.h>
#include <math.h>
#include <stdint.h>

#define HFD 64
#define WFD 64
#define CIN 1280
#define CCAP 256
#define NCAPS 19
#define DK 64
#define DV 16
#define NP 48              // 0..18 score-base, 19 act-logit, 20..35 V, 36..47 zero pad
#define BATCH 8
#define NINST 32
#define NPTS 256
#define NPIX (HFD*WFD)     // 4096
#define PKTOT (BATCH*NPIX*NP)

// ---- device scratch (no cudaMalloc allowed) ----
__device__ uint32_t g_Wbh[(CIN/2)*NP];        // folded weights, bf16 hi, packed k-pairs
__device__ uint32_t g_Wbl[(CIN/2)*NP];        // bf16 lo residual, packed k-pairs
__device__ float    g_const[NP];
__device__ float    g_QWrel[2*NCAPS];         // rel-pos rows of 0.125*Q@Wk^T
__device__ float    g_pk[2*PKTOT];            // two K-split partial buffers (12.6 MB)

__device__ __forceinline__ uint32_t packbf2(float x, float y) {
    __nv_bfloat162 h = __floats2bfloat162_rn(x, y);
    return *(uint32_t*)&h;
}

// ============ prep v5: ONE j-tile of 256 (dynamic smem ~107KB), grid 160, 512 thr ============
// T[c][o] = sum_j Wp[j][c]*Wk[j][o] (o<64) ; V[c][d] = sum_j Wp[j][c]*Wv[j][d]
// Wf[c][col<19] = 0.125*sum_o Q[col][o]*T[c][o] ; col 19 = Wa[c] ; cols 20..35 = V
#define CT 8                // channels per block
#define KC 80               // combined cols: 0..63 Wk, 64..79 Wv
// dynamic smem layout (floats):
#define OFF_WP   0            // [256][8]     2048
#define OFF_K    2048         // [256][80]    20480
#define OFF_BP   22528        // [256]        256
#define OFF_Q    22784        // [19][65]     1235
#define OFF_TSP  24019        // [4][8][81]   2592
#define OFF_TS   26611        // [8][81]      648
#define OFF_CB   27259        // [80]         80
#define PREP_SMEM_FLOATS 27339
#define PREP_SMEM_BYTES (PREP_SMEM_FLOATS*4)

__global__ __launch_bounds__(512) void prep_kernel(
    const float* __restrict__ Wp, const float* __restrict__ Wa,
    const float* __restrict__ Q,  const float* __restrict__ Wk,
    const float* __restrict__ Wv, const float* __restrict__ bp,
    const float* __restrict__ ba, const float* __restrict__ bk,
    const float* __restrict__ bv)
{
    extern __shared__ float sm[];
    float* wpS = sm + OFF_WP;
    float* kS  = sm + OFF_K;
    float* bpS = sm + OFF_BP;
    float* qS  = sm + OFF_Q;
    float* TSp = sm + OFF_TSP;
    float* TS  = sm + OFF_TS;
    float* cbS = sm + OFF_CB;

    int t  = threadIdx.x;
    int c0 = blockIdx.x * CT;
    int cl = t & 7;                   // channel 0..7
    int cg = (t >> 3) & 15;           // col group 0..15
    int g5 = cg * 5;                  // col base 0..75
    int js = t >> 7;                  // j-quarter 0..3 (64 j each)
    bool blk0 = (blockIdx.x == 0);

    // ---- single load phase ----
    for (int i = t; i < NCAPS*64; i += 512) {
        int row = i >> 6, o = i & 63;
        qS[row*65 + o] = Q[i];
    }
    // Wp: 256 rows x 8 ch = 512 float4 (1 each)
    {
        int jj = t >> 1, c4 = (t & 1) * 4;
        *(float4*)&wpS[jj*CT + c4] = *(const float4*)&Wp[(size_t)jj*CIN + c0 + c4];
    }
    // Wk into kS cols 0..63: 4096 float4 (8 each)
    #pragma unroll
    for (int r = 0; r < 8; ++r) {
        int i = t + 512*r;
        int jj = i >> 4, o4 = (i & 15) * 4;
        *(float4*)&kS[jj*KC + o4] = *(const float4*)&Wk[(size_t)jj*DK + o4];
    }
    // Wv into kS cols 64..79: 1024 float4 (2 each)
    #pragma unroll
    for (int r = 0; r < 2; ++r) {
        int i = t + 512*r;
        int jj = i >> 2, d4 = (i & 3) * 4;
        *(float4*)&kS[jj*KC + 64 + d4] = *(const float4*)&Wv[(size_t)jj*DV + d4];
    }
    if (blk0 && t < 256) bpS[t] = bp[t];
    __syncthreads();

    // ---- single compute phase: this thread's 64-j slice ----
    float acc[5] = {0.f, 0.f, 0.f, 0.f, 0.f};
    {
        int jb = js * 64;
        #pragma unroll 4
        for (int u = 0; u < 64; ++u) {
            int jj = jb + u;
            float a = wpS[jj*CT + cl];
            #pragma unroll
            for (int r = 0; r < 5; ++r) acc[r] += a * kS[jj*KC + g5 + r];
        }
    }
    if (blk0 && t < KC) {
        float cb = 0.f;
        #pragma unroll 8
        for (int jj = 0; jj < 256; ++jj) cb += bpS[jj] * kS[jj*KC + t];
        cbS[t] = cb;
    }
    #pragma unroll
    for (int r = 0; r < 5; ++r) TSp[(js*CT + cl)*81 + g5 + r] = acc[r];
    __syncthreads();

    // reduce 4 j-partials: 8*80 outputs
    for (int i = t; i < CT*KC; i += 512) {
        int c = i / KC, o = i % KC;
        TS[c*81 + o] = TSp[(0*CT + c)*81 + o] + TSp[(1*CT + c)*81 + o]
                     + TSp[(2*CT + c)*81 + o] + TSp[(3*CT + c)*81 + o];
    }
    __syncthreads();

    // output: 4 channel-pairs x 48 cols = 192 outputs
    if (t < (CT/2)*NP) {
        int cp = t / NP, col = t % NP;
        int c = c0 + 2*cp;
        float s0, s1;
        if (col < NCAPS) {
            float a0 = 0.f, a1 = 0.f;
            const float* q  = &qS[col*65];
            const float* t0 = &TS[(2*cp  )*81];
            const float* t1 = &TS[(2*cp+1)*81];
            #pragma unroll 8
            for (int o = 0; o < 64; ++o) {
                float qq = q[o];
                a0 += qq * t0[o];
                a1 += qq * t1[o];
            }
            s0 = 0.125f*a0; s1 = 0.125f*a1;
        } else if (col == NCAPS) {
            s0 = Wa[c]; s1 = Wa[c + 1];
        } else if (col < 20 + DV) {
            int d = col - 20;
            s0 = TS[(2*cp)*81 + 64 + d]; s1 = TS[(2*cp+1)*81 + 64 + d];
        } else { s0 = 0.f; s1 = 0.f; }
        __nv_bfloat162 h = __floats2bfloat162_rn(s0, s1);
        g_Wbh[(c >> 1)*NP + col] = *(uint32_t*)&h;
        g_Wbl[(c >> 1)*NP + col] =
            packbf2(s0 - __bfloat162float(h.x), s1 - __bfloat162float(h.y));
    }

    if (blk0) {
        if (t >= 256 && t < 256 + NP) {
            int o = t - 256;
            float s;
            if (o < NCAPS) {
                float a = 0.f;
                #pragma unroll 8
                for (int k = 0; k < 64; ++k) a += qS[o*65 + k] * (cbS[k] + bk[k]);
                s = 0.125f * a;
            } else if (o == NCAPS) s = ba[0];
            else if (o < 20 + DV) s = cbS[64 + (o - 20)] + bv[o - 20];
            else s = 0.f;
            g_const[o] = s;
        }
        if (t >= 320 && t < 320 + 2*NCAPS) {
            int i = t - 320;
            int cc = i % NCAPS, which = i / NCAPS;
            const float* wkrow = Wk + (size_t)(256 + which)*DK;
            float s = 0.f;
            #pragma unroll 8
            for (int o = 0; o < 64; ++o) s += qS[cc*65 + o] * wkrow[o];
            g_QWrel[which*NCAPS + cc] = 0.125f * s;
        }
    }
}

// ============ GEMM: pk = feat @ Wfold, 3xBF16 mma, BM=64, K-split 2, grid 1024 (verified) ============
#define BM 64
#define BK 16
#define AS_STRIDE 68
#define BS_STRIDE 56
#define NKCH_H 40          // k-chunks per split (K=640 each)

#define CP_ASYNC16(dst_s32, src) \
    asm volatile("cp.async.cg.shared.global [%0], [%1], 16;\n" :: "r"(dst_s32), "l"(src))
#define CP_COMMIT() asm volatile("cp.async.commit_group;\n")

__device__ __forceinline__ void mma_bf16(float* d, const uint32_t* a, uint32_t b0, uint32_t b1) {
    asm volatile(
        "mma.sync.aligned.m16n8k16.row.col.f32.bf16.bf16.f32 "
        "{%0,%1,%2,%3},{%4,%5,%6,%7},{%8,%9},{%0,%1,%2,%3};\n"
        : "+f"(d[0]), "+f"(d[1]), "+f"(d[2]), "+f"(d[3])
        : "r"(a[0]), "r"(a[1]), "r"(a[2]), "r"(a[3]), "r"(b0), "r"(b1));
}

__global__ __launch_bounds__(128) void gemm_kernel(const float* __restrict__ feat) {
    __shared__ __align__(16) float smem[4016];
    int t = threadIdx.x;
    int mtile = blockIdx.x >> 1;
    int split = blockIdx.x & 1;
    int m0 = mtile * BM;
    int b  = m0 / NPIX;
    int pix0 = m0 % NPIX;
    int kbase = split * (CIN/2);         // 0 or 640
    const float* aBase = feat + (size_t)b*CIN*NPIX + pix0;

    if (t < NP) smem[3968 + t] = split ? 0.f : g_const[t];

    int lane = t & 31, w = t >> 5;
    int gid = lane >> 2, tig = lane & 3;
    int wm = w * 16;

    uint32_t s_as = (uint32_t)__cvta_generic_to_shared(smem);
    uint32_t s_bh = s_as + 2176*4;
    uint32_t s_bl = s_as + 3072*4;

    int a_kk0 = t >> 4;              // 0..7 (second: +8)
    int a_m0  = (t & 15) * 4;
    int b_kp  = t / 12;              // 0..7 (t<96)
    int b_n0  = (t % 12) * 4;

#define LOAD_STAGE(p, k0)                                                            \
    do {                                                                             \
        CP_ASYNC16(s_as + ((p)*1088 + a_kk0*AS_STRIDE + a_m0)*4,                     \
                   aBase + (size_t)((k0)+a_kk0)*NPIX + a_m0);                        \
        CP_ASYNC16(s_as + ((p)*1088 + (a_kk0+8)*AS_STRIDE + a_m0)*4,                 \
                   aBase + (size_t)((k0)+a_kk0+8)*NPIX + a_m0);                      \
        if (t < 96) {                                                                \
            CP_ASYNC16(s_bh + ((p)*448 + b_kp*BS_STRIDE + b_n0)*4,                   \
                       &g_Wbh[((k0)/2 + b_kp)*NP + b_n0]);                           \
            CP_ASYNC16(s_bl + ((p)*448 + b_kp*BS_STRIDE + b_n0)*4,                   \
                       &g_Wbl[((k0)/2 + b_kp)*NP + b_n0]);                           \
        }                                                                            \
        CP_COMMIT();                                                                 \
    } while (0)

    LOAD_STAGE(0, kbase);

    float d[6][4];
    #pragma unroll
    for (int nt = 0; nt < 6; ++nt)
        #pragma unroll
        for (int i = 0; i < 4; ++i) d[nt][i] = 0.f;

    for (int kc = 0; kc < NKCH_H; ++kc) {
        if (kc + 1 < NKCH_H) {
            LOAD_STAGE((kc+1) & 1, kbase + (kc+1)*BK);
            asm volatile("cp.async.wait_group 1;\n");
        } else {
            asm volatile("cp.async.wait_group 0;\n");
        }
        __syncthreads();

        const float*    As_ = smem + (kc&1)*1088;
        const uint32_t* Bh  = (const uint32_t*)(smem + 2176) + (kc&1)*448;
        const uint32_t* Bl  = (const uint32_t*)(smem + 3072) + (kc&1)*448;

        int m = wm + gid;
        float L00 = As_[(2*tig  )*AS_STRIDE + m];
        float L01 = As_[(2*tig+1)*AS_STRIDE + m];
        float L08 = As_[(2*tig+8)*AS_STRIDE + m];
        float L09 = As_[(2*tig+9)*AS_STRIDE + m];
        float M00 = As_[(2*tig  )*AS_STRIDE + m + 8];
        float M01 = As_[(2*tig+1)*AS_STRIDE + m + 8];
        float M08 = As_[(2*tig+8)*AS_STRIDE + m + 8];
        float M09 = As_[(2*tig+9)*AS_STRIDE + m + 8];

        uint32_t ah[4], al[4];
        {
            __nv_bfloat162 h;
            h = __floats2bfloat162_rn(L00, L01); ah[0] = *(uint32_t*)&h;
            al[0] = packbf2(L00 - __bfloat162float(h.x), L01 - __bfloat162float(h.y));
            h = __floats2bfloat162_rn(M00, M01); ah[1] = *(uint32_t*)&h;
            al[1] = packbf2(M00 - __bfloat162float(h.x), M01 - __bfloat162float(h.y));
            h = __floats2bfloat162_rn(L08, L09); ah[2] = *(uint32_t*)&h;
            al[2] = packbf2(L08 - __bfloat162float(h.x), L09 - __bfloat162float(h.y));
            h = __floats2bfloat162_rn(M08, M09); ah[3] = *(uint32_t*)&h;
            al[3] = packbf2(M08 - __bfloat162float(h.x), M09 - __bfloat162float(h.y));
        }

        #pragma unroll
        for (int nt = 0; nt < 6; ++nt) {
            int n = nt*8 + gid;
            uint32_t bh0 = Bh[ tig   *BS_STRIDE + n];
            uint32_t bh1 = Bh[(tig+4)*BS_STRIDE + n];
            uint32_t bl0 = Bl[ tig   *BS_STRIDE + n];
            uint32_t bl1 = Bl[(tig+4)*BS_STRIDE + n];
            mma_bf16(d[nt], ah, bh0, bh1);
            mma_bf16(d[nt], ah, bl0, bl1);
            mma_bf16(d[nt], al, bh0, bh1);
        }
        __syncthreads();
    }

    float* Cs = smem;
    #pragma unroll
    for (int nt = 0; nt < 6; ++nt) {
        int col = nt*8 + tig*2;
        Cs[(wm + gid    )*NP + col    ] = d[nt][0];
        Cs[(wm + gid    )*NP + col + 1] = d[nt][1];
        Cs[(wm + gid + 8)*NP + col    ] = d[nt][2];
        Cs[(wm + gid + 8)*NP + col + 1] = d[nt][3];
    }
    __syncthreads();
    const float4* csts4 = (const float4*)(smem + 3968);
    float4* outBase = (float4*)(g_pk + (size_t)split*PKTOT + (size_t)m0*NP);
    #pragma unroll
    for (int it = 0; it < 6; ++it) {
        int i = t + 128*it;              // 768 float4 total
        float4 v = ((const float4*)Cs)[i];
        float4 c = csts4[i % 12];
        v.x += c.x; v.y += c.y; v.z += c.z; v.w += c.w;
        outBase[i] = v;
    }
}

// ============ route: dedupe + softmax routing (sums two K-split partials, verified) ============
__global__ __launch_bounds__(256) void route_kernel(
    const int* __restrict__ pts,
    const float* __restrict__ Wv,
    const float* __restrict__ Wl,
    const float* __restrict__ bl,
    float* __restrict__ out)
{
    __shared__ unsigned bitmap[NPIX/32];
    __shared__ int counts[NPIX/32];
    __shared__ int offs[NPIX/32 + 1];
    __shared__ unsigned short cells[NPTS];
    __shared__ int sumY, sumX;
    __shared__ float scores[NCAPS][NPTS];
    __shared__ float vmatS[DV][NPTS];
    __shared__ float qwy[NCAPS], qwx[NCAPS];
    __shared__ float relVy[DV], relVx[DV], Wls[DV];

    int t  = threadIdx.x;
    int bi = blockIdx.x;
    const int* pbase = pts + (size_t)bi*2*NPTS;

    if (t < NPIX/32) bitmap[t] = 0u;
    if (t < NCAPS) { qwy[t] = g_QWrel[t]; qwx[t] = g_QWrel[NCAPS + t]; }
    if (t < DV) { relVy[t] = Wv[256*DV + t]; relVx[t] = Wv[257*DV + t]; Wls[t] = Wl[t]; }
    if (t == 0) { sumY = 0; sumX = 0; }
    __syncthreads();

    {
        int y = pbase[t] >> 4;
        int x = pbase[NPTS + t] >> 4;
        int key = y*WFD + x;
        atomicOr(&bitmap[key >> 5], 1u << (key & 31));
    }
    __syncthreads();
    if (t < NPIX/32) counts[t] = __popc(bitmap[t]);
    __syncthreads();
    if (t < 32) {
        int c0 = counts[t*4], c1 = counts[t*4+1], c2 = counts[t*4+2], c3 = counts[t*4+3];
        int s = c0 + c1 + c2 + c3;
        int run = s;
        #pragma unroll
        for (int off = 1; off < 32; off <<= 1) {
            int v = __shfl_up_sync(0xffffffffu, run, off);
            if (t >= off) run += v;
        }
        int excl = run - s;
        offs[t*4]   = excl;
        offs[t*4+1] = excl + c0;
        offs[t*4+2] = excl + c0 + c1;
        offs[t*4+3] = excl + c0 + c1 + c2;
        if (t == 31) offs[128] = run;
    }
    __syncthreads();
    if (t < NPIX/32) {
        unsigned bits = bitmap[t];
        int idx = offs[t];
        int sy = 0, sx = 0;
        while (bits) {
            int bpos = __ffs(bits) - 1;
            bits &= bits - 1;
            int cell = t*32 + bpos;
            cells[idx++] = (unsigned short)cell;
            sy += cell >> 6;
            sx += cell & 63;
        }
        if (counts[t]) { atomicAdd(&sumY, sy); atomicAdd(&sumX, sx); }
    }
    __syncthreads();

    int U = offs[NPIX/32];
    float nfl = (float)(U > 0 ? U : 1);
    float meanY = (float)sumY / nfl;
    float meanX = (float)sumX / nfl;

    if (t < U) {
        int cell = cells[t];
        size_t base = ((size_t)(bi >> 5)*NPIX + cell)*NP;
        const float4* pk4a = (const float4*)&g_pk[base];
        const float4* pk4b = (const float4*)&g_pk[PKTOT + base];
        float4 q[9];
        #pragma unroll
        for (int i = 0; i < 9; ++i) {
            float4 a = pk4a[i], b4 = pk4b[i];
            a.x += b4.x; a.y += b4.y; a.z += b4.z; a.w += b4.w;
            q[i] = a;
        }
        const float* pk = (const float*)q;

        float ry = ((float)(cell >> 6) - meanY) * (1.f/HFD);
        float rx = ((float)(cell & 63) - meanX) * (1.f/WFD);
        float act = 1.f/(1.f + expf(-pk[19]));
        float la  = logf(act + 1e-6f);
        #pragma unroll
        for (int c = 0; c < NCAPS; ++c)
            scores[c][t] = pk[c] + ry*qwy[c] + rx*qwx[c] + la;
        #pragma unroll
        for (int dd = 0; dd < DV; ++dd)
            vmatS[dd][t] = pk[20 + dd] + ry*relVy[dd] + rx*relVx[dd];
    }
    __syncthreads();

    int warp = t >> 5, lane = t & 31;
    for (int c = warp; c < NCAPS; c += 8) {
        float mx = -1e30f;
        for (int j = lane; j < U; j += 32) mx = fmaxf(mx, scores[c][j]);
        #pragma unroll
        for (int off = 16; off; off >>= 1) mx = fmaxf(mx, __shfl_xor_sync(0xffffffffu, mx, off));
        float se = 0.f;
        float acc[DV];
        #pragma unroll
        for (int dd = 0; dd < DV; ++dd) acc[dd] = 0.f;
        for (int j = lane; j < U; j += 32) {
            float e = expf(scores[c][j] - mx);
            se += e;
            #pragma unroll
            for (int dd = 0; dd < DV; ++dd) acc[dd] += e*vmatS[dd][j];
        }
        #pragma unroll
        for (int off = 16; off; off >>= 1) {
            se += __shfl_xor_sync(0xffffffffu, se, off);
            #pragma unroll
            for (int dd = 0; dd < DV; ++dd) acc[dd] += __shfl_xor_sync(0xffffffffu, acc[dd], off);
        }
        if (lane == 0) {
            float o = bl[0];
            float inv = 1.f/se;
            #pragma unroll
            for (int dd = 0; dd < DV; ++dd) o += (acc[dd]*inv)*Wls[dd];
            out[bi*NCAPS + c] = 1.f/(1.f + expf(-o));
        }
    }
}

extern "C" void kernel_launch(void* const* d_in, const int* in_sizes, int n_in,
                              void* d_out, int out_size) {
    const float* feat = (const float*)d_in[0];
    const float* Wp   = (const float*)d_in[1];
    const float* bp   = (const float*)d_in[2];
    const float* Wa   = (const float*)d_in[3];
    const float* ba   = (const float*)d_in[4];
    const float* Q    = (const float*)d_in[5];
    const float* Wk   = (const float*)d_in[6];
    const float* bk   = (const float*)d_in[7];
    const float* Wv   = (const float*)d_in[8];
    const float* bv   = (const float*)d_in[9];
    const float* Wl   = (const float*)d_in[10];
    const float* bl   = (const float*)d_in[11];
    const int*   pts  = (const int*)d_in[12];
    float* out = (float*)d_out;

    cudaFuncSetAttribute(prep_kernel, cudaFuncAttributeMaxDynamicSharedMemorySize,
                         PREP_SMEM_BYTES);
    prep_kernel<<<CIN/CT, 512, PREP_SMEM_BYTES>>>(Wp, Wa, Q, Wk, Wv, bp, ba, bk, bv);
    gemm_kernel<<<(BATCH*NPIX)/BM * 2, 128>>>(feat);
    route_kernel<<<BATCH*NINST, 256>>>(pts, Wv, Wl, bl, out);
}